// round 12
// baseline (speedup 1.0000x reference)
#include <cuda_runtime.h>
#include <cuda_bf16.h>
#include <math.h>
#include <stdint.h>

// ---------------------------------------------------------------------------
// SingleStreamBlock — tf32 mma.sync + cp.async pipeline + ldmatrix fragments
// Activations tf32-rounded at source; weights rounded per-fragment (cvt.rna).
// cat_kernel eliminated: GEMM1 writes h|gelu->cat, PV writes attn->cat.
// Shapes: B=1, L=2048, D=3072, H=24, Dh=128, QKV=9216, CAT=15360
// ---------------------------------------------------------------------------

#define L_   2048
#define D_   3072
#define H_   24
#define DH_  128
#define QKV_ 9216
#define W1N_ 21504      // QKV + 4*D
#define CAT_ 15360      // D + 4*D
#define EPS_ 1e-6f

// Scratch (device globals: allocation-free)
__device__ float g_sv[D_];
__device__ float g_m[3 * D_];
__device__ float g_xmod[(size_t)L_ * D_];
__device__ float g_h[(size_t)L_ * QKV_];        // compact: qkv only
__device__ float g_S[(size_t)H_ * L_ * L_];
__device__ float g_cat[(size_t)L_ * CAT_];      // [attn | gelu(mlp)]

__device__ __forceinline__ uint32_t f2tf32(float x) {
    uint32_t r;
    asm("cvt.rna.tf32.f32 %0, %1;" : "=r"(r) : "f"(x));
    return r;
}
__device__ __forceinline__ float rnaf(float x) {    // tf32-rounded fp32 value
    return __uint_as_float(f2tf32(x));
}

// ---------------------------------------------------------------------------
// small elementwise / reduction kernels
// ---------------------------------------------------------------------------
__global__ void silu_init(const float* __restrict__ v, const float* __restrict__ b,
                          float* __restrict__ sv, float* __restrict__ m) {
    int i = blockIdx.x * blockDim.x + threadIdx.x;
    if (i < D_) {
        float x = v[i];
        sv[i] = x / (1.0f + expf(-x));
    }
    if (i < 3 * D_) m[i] = b[i];
}

__global__ void mod_gemv(const float* __restrict__ sv, const float* __restrict__ w,
                         float* __restrict__ m) {
    __shared__ float s[384];
    int i0 = blockIdx.y * 384;
    for (int i = threadIdx.x; i < 384; i += 128) s[i] = sv[i0 + i];
    __syncthreads();
    int j = blockIdx.x * 128 + threadIdx.x;
    float acc = 0.f;
#pragma unroll 8
    for (int i = 0; i < 384; i++) acc += s[i] * w[(size_t)(i0 + i) * (3 * D_) + j];
    atomicAdd(&m[j], acc);
}

__global__ void ln_mod(const float* __restrict__ x, const float* __restrict__ m,
                       float* __restrict__ xmod) {
    __shared__ float r1[8], r2[8], bc[2];
    int row = blockIdx.x, t = threadIdx.x;
    const float* xr = x + (size_t)row * D_;
    float sum = 0.f, ss = 0.f;
    for (int i = t; i < D_; i += 256) {
        float v = xr[i];
        sum += v; ss += v * v;
    }
#pragma unroll
    for (int o = 16; o > 0; o >>= 1) {
        sum += __shfl_xor_sync(0xffffffffu, sum, o);
        ss  += __shfl_xor_sync(0xffffffffu, ss,  o);
    }
    if ((t & 31) == 0) { r1[t >> 5] = sum; r2[t >> 5] = ss; }
    __syncthreads();
    if (t == 0) {
        float a = 0.f, b = 0.f;
        for (int w = 0; w < 8; w++) { a += r1[w]; b += r2[w]; }
        bc[0] = a; bc[1] = b;
    }
    __syncthreads();
    float mu  = bc[0] * (1.0f / D_);
    float var = bc[1] * (1.0f / D_) - mu * mu;
    float inv = rsqrtf(var + EPS_);
    const float* shift = m;
    const float* scale = m + D_;
    float* orow = xmod + (size_t)row * D_;
    for (int i = t; i < D_; i += 256) {
        float v = (xr[i] - mu) * inv;
        orow[i] = rnaf((1.0f + scale[i]) * v + shift[i]);
    }
}

// RMSNorm + RoPE for q,k in compact h [L][QKV_]; outputs tf32-rounded
__global__ void rmsrope(float* __restrict__ h, const float* __restrict__ pe,
                        const float* __restrict__ qs, const float* __restrict__ ks) {
    __shared__ float red[2];
    int l = blockIdx.x, hh = blockIdx.y, t = threadIdx.x;
    float* base = h + (size_t)l * QKV_ + hh * DH_;
    const float* p = pe + (size_t)l * 256 + t * 4;
    for (int s = 0; s < 2; s++) {
        float* ptr = base + s * D_;
        const float* g = s ? ks : qs;
        float a = ptr[2 * t], b = ptr[2 * t + 1];
        float sq = a * a + b * b;
#pragma unroll
        for (int o = 16; o > 0; o >>= 1) sq += __shfl_xor_sync(0xffffffffu, sq, o);
        if ((t & 31) == 0) red[t >> 5] = sq;
        __syncthreads();
        float tot = red[0] + red[1];
        float r = rsqrtf(tot * (1.0f / DH_) + EPS_);
        float na = a * r * g[2 * t];
        float nb = b * r * g[2 * t + 1];
        ptr[2 * t]     = rnaf(p[0] * na + p[1] * nb);
        ptr[2 * t + 1] = rnaf(p[2] * na + p[3] * nb);
        __syncthreads();
    }
}

__global__ void softmax2048(float* __restrict__ S) {
    __shared__ float r[8], bc;
    int t = threadIdx.x;
    float* row = S + (size_t)blockIdx.x * L_;
    float v[8];
    float mx = -1e30f;
#pragma unroll
    for (int i = 0; i < 8; i++) { v[i] = row[t + i * 256]; mx = fmaxf(mx, v[i]); }
#pragma unroll
    for (int o = 16; o > 0; o >>= 1) mx = fmaxf(mx, __shfl_xor_sync(0xffffffffu, mx, o));
    if ((t & 31) == 0) r[t >> 5] = mx;
    __syncthreads();
    if (t == 0) {
        float m2 = r[0];
        for (int w = 1; w < 8; w++) m2 = fmaxf(m2, r[w]);
        bc = m2;
    }
    __syncthreads();
    mx = bc;
    float sum = 0.f;
#pragma unroll
    for (int i = 0; i < 8; i++) { v[i] = expf(v[i] - mx); sum += v[i]; }
#pragma unroll
    for (int o = 16; o > 0; o >>= 1) sum += __shfl_xor_sync(0xffffffffu, sum, o);
    if ((t & 31) == 0) r[t >> 5] = sum;
    __syncthreads();
    if (t == 0) {
        float s2 = 0.f;
        for (int w = 0; w < 8; w++) s2 += r[w];
        bc = s2;
    }
    __syncthreads();
    float inv = 1.0f / bc;
#pragma unroll
    for (int i = 0; i < 8; i++) row[t + i * 256] = rnaf(v[i] * inv);
}

__device__ __forceinline__ float gelu_tanh(float x) {
    float x3 = x * x * x;
    return 0.5f * x * (1.0f + tanhf(0.7978845608028654f * (x + 0.044715f * x3)));
}

// ---------------------------------------------------------------------------
// tf32 mma.sync GEMM: cp.async 4-stage + ldmatrix fragment loads.
// BM=128, BK=16, BN in {128,256}. 256 thr = 8 warps (2m x 4n).
// A smem [m][k] stride 20 (ldmatrix-friendly, conflict-free).
// B NT smem [n][k] stride 20 (ldmatrix).  B NN smem [k][n] stride BN+8 (LDS).
// CVTB: apply cvt.rna to B fragments (raw fp32 weights).
// EPI 1: *alpha | 2: rna (PV->cat) | 3: xres+gate*(acc+bias) | 4: h|gelu->cat
// ---------------------------------------------------------------------------
#define CPA16(dst, src) \
    asm volatile("cp.async.cg.shared.global [%0], [%1], 16;" :: "r"(dst), "l"(src))
#define CP_COMMIT() asm volatile("cp.async.commit_group;" ::: "memory")
#define CP_WAIT2()  asm volatile("cp.async.wait_group 2;" ::: "memory")

__device__ __forceinline__ void mma_tf32(float c[4], const uint32_t a[4],
                                         const uint32_t b[2]) {
    asm volatile(
        "mma.sync.aligned.m16n8k8.row.col.f32.tf32.tf32.f32 "
        "{%0,%1,%2,%3}, {%4,%5,%6,%7}, {%8,%9}, {%0,%1,%2,%3};"
        : "+f"(c[0]), "+f"(c[1]), "+f"(c[2]), "+f"(c[3])
        : "r"(a[0]), "r"(a[1]), "r"(a[2]), "r"(a[3]), "r"(b[0]), "r"(b[1]));
}
__device__ __forceinline__ void ldsm4(uint32_t* r, uint32_t addr) {
    asm volatile("ldmatrix.sync.aligned.m8n8.x4.shared.b16 {%0,%1,%2,%3}, [%4];"
                 : "=r"(r[0]), "=r"(r[1]), "=r"(r[2]), "=r"(r[3]) : "r"(addr));
}

template <int EPI, bool NT, int BN, bool CVTB>
__global__ __launch_bounds__(256) void gemm_cp(
    const float* __restrict__ A, const float* __restrict__ B, float* __restrict__ C,
    float* __restrict__ C2,
    int K, int lda, int ldb, int ldc,
    long long sA, long long sB, long long sC, float alpha,
    const float* __restrict__ bias, const float* __restrict__ xres,
    const float* __restrict__ gate)
{
    constexpr int AW = 128 * 20;                         // A stage words
    constexpr int BW = NT ? BN * 20 : 16 * (BN + 8);     // B stage words
    constexpr int STGW = AW + BW;
    constexpr int NJ = BN / 32;
    extern __shared__ float sm[];

    A += (long long)blockIdx.z * sA;
    B += (long long)blockIdx.z * sB;
    C += (long long)blockIdx.z * sC;
    const int m0 = blockIdx.x * 128, n0 = blockIdx.y * BN;
    const int tid = threadIdx.x;
    const int warp = tid >> 5, lane = tid & 31;
    const int wm = (warp & 1) * 64;
    const int wn = (warp >> 1) * (BN / 4);
    const int g = lane >> 2, q = lane & 3;

    const uint32_t sbase = (uint32_t)__cvta_generic_to_shared(sm);

    // per-lane ldmatrix byte offsets (stage-relative)
    int aoff[4][2];
#pragma unroll
    for (int mi = 0; mi < 4; mi++)
#pragma unroll
        for (int ksp = 0; ksp < 2; ksp++)
            aoff[mi][ksp] = ((wm + mi * 16 + ((lane >> 3) & 1) * 8 + (lane & 7)) * 20
                             + ksp * 8 + ((lane >> 4) & 1) * 4) * 4;
    int boff[NJ / 2 > 0 ? NJ / 2 : 1][2];
    if (NT) {
#pragma unroll
        for (int njp = 0; njp < NJ / 2; njp++)
#pragma unroll
            for (int ksp = 0; ksp < 2; ksp++)
                boff[njp][ksp] = AW * 4 +
                    ((wn + njp * 16 + ((lane >> 4) & 1) * 8 + (lane & 7)) * 20
                     + ksp * 8 + ((lane >> 3) & 1) * 4) * 4;
    }

    float acc[4][NJ][4];
#pragma unroll
    for (int mi = 0; mi < 4; mi++)
#pragma unroll
        for (int nj = 0; nj < NJ; nj++)
#pragma unroll
            for (int e = 0; e < 4; e++) acc[mi][nj][e] = 0.f;

    const int nk = K >> 4;

    auto issue = [&](int kt, int s) {
        const uint32_t as = sbase + (uint32_t)(s * STGW * 4);
        const uint32_t bs = as + AW * 4;
        const int k0 = kt << 4;
#pragma unroll
        for (int i = 0; i < 2; i++) {
            int ch = tid + 256 * i;
            int r = ch >> 2, c = ch & 3;
            CPA16(as + (uint32_t)(r * 80 + c * 16),
                  A + (size_t)(m0 + r) * lda + k0 + c * 4);
        }
        if (NT) {
#pragma unroll
            for (int i = 0; i < BN / 64; i++) {
                int ch = tid + 256 * i;
                int r = ch >> 2, c = ch & 3;
                CPA16(bs + (uint32_t)(r * 80 + c * 16),
                      B + (size_t)(n0 + r) * ldb + k0 + c * 4);
            }
        } else {
#pragma unroll
            for (int i = 0; i < BN / 64; i++) {
                int ch = tid + 256 * i;
                int r = ch / (BN / 4), c = ch % (BN / 4);
                CPA16(bs + (uint32_t)(r * (BN + 8) * 4 + c * 16),
                      B + (size_t)(k0 + r) * ldb + n0 + c * 4);
            }
        }
    };

    for (int s = 0; s < 3; s++) {
        if (s < nk) issue(s, s);
        CP_COMMIT();
    }

    for (int it = 0; it < nk; it++) {
        CP_WAIT2();
        __syncthreads();
        if (it + 3 < nk) issue(it + 3, (it + 3) & 3);
        CP_COMMIT();

        const uint32_t stg_u = sbase + (uint32_t)((it & 3) * STGW * 4);
        const float* bs = sm + (size_t)(it & 3) * STGW + AW;
#pragma unroll
        for (int ksp = 0; ksp < 2; ksp++) {
            const int kq = ksp * 8 + q;
            uint32_t af[4][4];
#pragma unroll
            for (int mi = 0; mi < 4; mi++) ldsm4(af[mi], stg_u + aoff[mi][ksp]);
            uint32_t bf[NJ][2];
            if (NT) {
#pragma unroll
                for (int njp = 0; njp < NJ / 2; njp++) {
                    uint32_t t4[4];
                    ldsm4(t4, stg_u + boff[njp][ksp]);
                    bf[2 * njp][0]     = t4[0];
                    bf[2 * njp][1]     = t4[1];
                    bf[2 * njp + 1][0] = t4[2];
                    bf[2 * njp + 1][1] = t4[3];
                }
            } else {
#pragma unroll
                for (int nj = 0; nj < NJ; nj++) {
                    const float* bp = bs + kq * (BN + 8) + wn + nj * 8 + g;
                    float x0 = bp[0], x1 = bp[4 * (BN + 8)];
                    bf[nj][0] = CVTB ? f2tf32(x0) : __float_as_uint(x0);
                    bf[nj][1] = CVTB ? f2tf32(x1) : __float_as_uint(x1);
                }
            }
#pragma unroll
            for (int mi = 0; mi < 4; mi++)
#pragma unroll
                for (int nj = 0; nj < NJ; nj++)
                    mma_tf32(acc[mi][nj], af[mi], bf[nj]);
        }
    }

    // epilogue
#pragma unroll
    for (int mi = 0; mi < 4; mi++) {
#pragma unroll
        for (int hh = 0; hh < 2; hh++) {
            size_t row = (size_t)(m0 + wm + mi * 16 + g + hh * 8);
#pragma unroll
            for (int nj = 0; nj < NJ; nj++) {
                int col = n0 + wn + nj * 8 + 2 * q;
                float v0 = acc[mi][nj][hh * 2 + 0];
                float v1 = acc[mi][nj][hh * 2 + 1];
                if (EPI == 1) {
                    v0 *= alpha; v1 *= alpha;
                    *(float2*)(C + row * ldc + col) = make_float2(v0, v1);
                } else if (EPI == 2) {
                    *(float2*)(C + row * ldc + col) = make_float2(rnaf(v0), rnaf(v1));
                } else if (EPI == 3) {
                    v0 = xres[row * ldc + col]     + gate[col]     * (v0 + bias[col]);
                    v1 = xres[row * ldc + col + 1] + gate[col + 1] * (v1 + bias[col + 1]);
                    *(float2*)(C + row * ldc + col) = make_float2(v0, v1);
                } else if (EPI == 4) {
                    v0 += bias[col]; v1 += bias[col + 1];
                    if (col < QKV_) {
                        *(float2*)(C + row * QKV_ + col) =
                            make_float2(rnaf(v0), rnaf(v1));
                    } else {
                        *(float2*)(C2 + row * CAT_ + D_ + (col - QKV_)) =
                            make_float2(rnaf(gelu_tanh(v0)), rnaf(gelu_tanh(v1)));
                    }
                }
            }
        }
    }
}

// stage sizes in bytes (x4 stages)
#define SMEM_NN256 ((128 * 20 + 16 * 264) * 4 * 4)   // 108544
#define SMEM_NT256 ((128 * 20 + 256 * 20) * 4 * 4)   // 122880
#define SMEM_NN128 ((128 * 20 + 16 * 136) * 4 * 4)   // 75776

// ---------------------------------------------------------------------------
// launcher
// ---------------------------------------------------------------------------
extern "C" void kernel_launch(void* const* d_in, const int* in_sizes, int n_in,
                              void* d_out, int out_size) {
    const float* x      = (const float*)d_in[0];
    const float* vec    = (const float*)d_in[1];
    const float* pe     = (const float*)d_in[2];
    const float* w_mod  = (const float*)d_in[3];
    const float* b_mod  = (const float*)d_in[4];
    const float* w1     = (const float*)d_in[5];
    const float* b1     = (const float*)d_in[6];
    const float* w2     = (const float*)d_in[7];
    const float* b2     = (const float*)d_in[8];
    const float* qscale = (const float*)d_in[9];
    const float* kscale = (const float*)d_in[10];
    float* out = (float*)d_out;

    float *sv, *m, *xmod, *h, *S, *cat;
    cudaGetSymbolAddress((void**)&sv,   g_sv);
    cudaGetSymbolAddress((void**)&m,    g_m);
    cudaGetSymbolAddress((void**)&xmod, g_xmod);
    cudaGetSymbolAddress((void**)&h,    g_h);
    cudaGetSymbolAddress((void**)&S,    g_S);
    cudaGetSymbolAddress((void**)&cat,  g_cat);

    cudaFuncSetAttribute(gemm_cp<4, false, 256, true>,
                         cudaFuncAttributeMaxDynamicSharedMemorySize, SMEM_NN256);
    cudaFuncSetAttribute(gemm_cp<1, true, 256, false>,
                         cudaFuncAttributeMaxDynamicSharedMemorySize, SMEM_NT256);
    cudaFuncSetAttribute(gemm_cp<2, false, 128, false>,
                         cudaFuncAttributeMaxDynamicSharedMemorySize, SMEM_NN128);
    cudaFuncSetAttribute(gemm_cp<3, false, 128, true>,
                         cudaFuncAttributeMaxDynamicSharedMemorySize, SMEM_NN128);

    // 1. sv = silu(vec); m = b_mod
    silu_init<<<(3 * D_) / 256, 256>>>(vec, b_mod, sv, m);
    // 2. m += sv @ w_mod
    mod_gemv<<<dim3(72, 8), 128>>>(sv, w_mod, m);
    // 3. layernorm + modulate (tf32-rounded output)
    ln_mod<<<L_, 256>>>(x, m, xmod);
    // 4. GEMM1: qkv -> h (compact), gelu(mlp) -> cat[:, D:]
    gemm_cp<4, false, 256, true><<<dim3(L_ / 128, W1N_ / 256), 256, SMEM_NN256>>>(
        xmod, w1, h, cat, D_, D_, W1N_, 0, 0, 0, 0, 1.0f, b1, nullptr, nullptr);
    // 5. q/k rmsnorm + rope (in-place in compact h, rounded)
    rmsrope<<<dim3(L_, H_), 64>>>(h, pe, qscale, kscale);
    // 6. S = Q @ K^T * Dh^-0.5
    gemm_cp<1, true, 256, false><<<dim3(L_ / 128, L_ / 256, H_), 256, SMEM_NT256>>>(
        h, h + D_, S, nullptr, DH_, QKV_, QKV_, L_,
        (long long)DH_, (long long)DH_, (long long)L_ * L_,
        0.08838834764831845f, nullptr, nullptr, nullptr);
    // 7. softmax rows (tf32-rounded probs)
    softmax2048<<<H_ * L_, 256>>>(S);
    // 8. PV: attn -> cat[:, 0:D] directly (rounded)
    gemm_cp<2, false, 128, false><<<dim3(L_ / 128, 1, H_), 256, SMEM_NN128>>>(
        S, h + 2 * D_, cat, nullptr, L_, L_, QKV_, CAT_,
        (long long)L_ * L_, (long long)DH_, (long long)DH_,
        1.0f, nullptr, nullptr, nullptr);
    // 9. out = x + gate * (cat @ w2 + b2)
    gemm_cp<3, false, 128, true><<<dim3(L_ / 128, D_ / 128), 256, SMEM_NN128>>>(
        cat, w2, out, nullptr, CAT_, CAT_, D_, D_, 0, 0, 0, 1.0f, b2, x, m + 2 * D_);
}

// round 13
// speedup vs baseline: 1.0317x; 1.0317x over previous
#include <cuda_runtime.h>
#include <cuda_bf16.h>
#include <math.h>
#include <stdint.h>

// ---------------------------------------------------------------------------
// SingleStreamBlock — tf32 mma.sync + cp.async, BN=128 everywhere, 2 CTAs/SM.
// Weights pre-rounded to tf32 once (no cvt in mainloop); activations rounded
// at source. Shapes: B=1, L=2048, D=3072, H=24, Dh=128, QKV=9216, CAT=15360
// ---------------------------------------------------------------------------

#define L_   2048
#define D_   3072
#define H_   24
#define DH_  128
#define QKV_ 9216
#define W1N_ 21504      // QKV + 4*D
#define CAT_ 15360      // D + 4*D
#define EPS_ 1e-6f

// Scratch (device globals: allocation-free)
__device__ float g_sv[D_];
__device__ float g_m[3 * D_];
__device__ float g_xmod[(size_t)L_ * D_];
__device__ float g_h[(size_t)L_ * QKV_];        // compact qkv
__device__ float g_S[(size_t)H_ * L_ * L_];
__device__ float g_cat[(size_t)L_ * CAT_];      // [attn | gelu(mlp)]
__device__ float g_w1r[(size_t)D_ * W1N_];      // tf32-rounded w1
__device__ float g_w2r[(size_t)CAT_ * D_];      // tf32-rounded w2

__device__ __forceinline__ uint32_t f2tf32(float x) {
    uint32_t r;
    asm("cvt.rna.tf32.f32 %0, %1;" : "=r"(r) : "f"(x));
    return r;
}
__device__ __forceinline__ float rnaf(float x) {
    return __uint_as_float(f2tf32(x));
}

// ---------------------------------------------------------------------------
// weight pre-round: grid-stride float4
// ---------------------------------------------------------------------------
__global__ void wround(const float4* __restrict__ w, float4* __restrict__ o, int n4) {
    int i = blockIdx.x * blockDim.x + threadIdx.x;
    int stride = gridDim.x * blockDim.x;
    for (; i < n4; i += stride) {
        float4 v = w[i];
        o[i] = make_float4(rnaf(v.x), rnaf(v.y), rnaf(v.z), rnaf(v.w));
    }
}

// ---------------------------------------------------------------------------
// small elementwise / reduction kernels
// ---------------------------------------------------------------------------
__global__ void silu_init(const float* __restrict__ v, const float* __restrict__ b,
                          float* __restrict__ sv, float* __restrict__ m) {
    int i = blockIdx.x * blockDim.x + threadIdx.x;
    if (i < D_) {
        float x = v[i];
        sv[i] = x / (1.0f + expf(-x));
    }
    if (i < 3 * D_) m[i] = b[i];
}

__global__ void mod_gemv(const float* __restrict__ sv, const float* __restrict__ w,
                         float* __restrict__ m) {
    __shared__ float s[384];
    int i0 = blockIdx.y * 384;
    for (int i = threadIdx.x; i < 384; i += 128) s[i] = sv[i0 + i];
    __syncthreads();
    int j = blockIdx.x * 128 + threadIdx.x;
    float acc = 0.f;
#pragma unroll 8
    for (int i = 0; i < 384; i++) acc += s[i] * w[(size_t)(i0 + i) * (3 * D_) + j];
    atomicAdd(&m[j], acc);
}

__global__ void ln_mod(const float* __restrict__ x, const float* __restrict__ m,
                       float* __restrict__ xmod) {
    __shared__ float r1[8], r2[8], bc[2];
    int row = blockIdx.x, t = threadIdx.x;
    const float* xr = x + (size_t)row * D_;
    float sum = 0.f, ss = 0.f;
    for (int i = t; i < D_; i += 256) {
        float v = xr[i];
        sum += v; ss += v * v;
    }
#pragma unroll
    for (int o = 16; o > 0; o >>= 1) {
        sum += __shfl_xor_sync(0xffffffffu, sum, o);
        ss  += __shfl_xor_sync(0xffffffffu, ss,  o);
    }
    if ((t & 31) == 0) { r1[t >> 5] = sum; r2[t >> 5] = ss; }
    __syncthreads();
    if (t == 0) {
        float a = 0.f, b = 0.f;
        for (int w = 0; w < 8; w++) { a += r1[w]; b += r2[w]; }
        bc[0] = a; bc[1] = b;
    }
    __syncthreads();
    float mu  = bc[0] * (1.0f / D_);
    float var = bc[1] * (1.0f / D_) - mu * mu;
    float inv = rsqrtf(var + EPS_);
    const float* shift = m;
    const float* scale = m + D_;
    float* orow = xmod + (size_t)row * D_;
    for (int i = t; i < D_; i += 256) {
        float v = (xr[i] - mu) * inv;
        orow[i] = rnaf((1.0f + scale[i]) * v + shift[i]);
    }
}

// RMSNorm + RoPE for q,k in compact h [L][QKV_]; tf32-rounded
__global__ void rmsrope(float* __restrict__ h, const float* __restrict__ pe,
                        const float* __restrict__ qs, const float* __restrict__ ks) {
    __shared__ float red[2];
    int l = blockIdx.x, hh = blockIdx.y, t = threadIdx.x;
    float* base = h + (size_t)l * QKV_ + hh * DH_;
    const float* p = pe + (size_t)l * 256 + t * 4;
    for (int s = 0; s < 2; s++) {
        float* ptr = base + s * D_;
        const float* g = s ? ks : qs;
        float a = ptr[2 * t], b = ptr[2 * t + 1];
        float sq = a * a + b * b;
#pragma unroll
        for (int o = 16; o > 0; o >>= 1) sq += __shfl_xor_sync(0xffffffffu, sq, o);
        if ((t & 31) == 0) red[t >> 5] = sq;
        __syncthreads();
        float tot = red[0] + red[1];
        float r = rsqrtf(tot * (1.0f / DH_) + EPS_);
        float na = a * r * g[2 * t];
        float nb = b * r * g[2 * t + 1];
        ptr[2 * t]     = rnaf(p[0] * na + p[1] * nb);
        ptr[2 * t + 1] = rnaf(p[2] * na + p[3] * nb);
        __syncthreads();
    }
}

__global__ void softmax2048(float* __restrict__ S) {
    __shared__ float r[8], bc;
    int t = threadIdx.x;
    float* row = S + (size_t)blockIdx.x * L_;
    float v[8];
    float mx = -1e30f;
#pragma unroll
    for (int i = 0; i < 8; i++) { v[i] = row[t + i * 256]; mx = fmaxf(mx, v[i]); }
#pragma unroll
    for (int o = 16; o > 0; o >>= 1) mx = fmaxf(mx, __shfl_xor_sync(0xffffffffu, mx, o));
    if ((t & 31) == 0) r[t >> 5] = mx;
    __syncthreads();
    if (t == 0) {
        float m2 = r[0];
        for (int w = 1; w < 8; w++) m2 = fmaxf(m2, r[w]);
        bc = m2;
    }
    __syncthreads();
    mx = bc;
    float sum = 0.f;
#pragma unroll
    for (int i = 0; i < 8; i++) { v[i] = expf(v[i] - mx); sum += v[i]; }
#pragma unroll
    for (int o = 16; o > 0; o >>= 1) sum += __shfl_xor_sync(0xffffffffu, sum, o);
    if ((t & 31) == 0) r[t >> 5] = sum;
    __syncthreads();
    if (t == 0) {
        float s2 = 0.f;
        for (int w = 0; w < 8; w++) s2 += r[w];
        bc = s2;
    }
    __syncthreads();
    float inv = 1.0f / bc;
#pragma unroll
    for (int i = 0; i < 8; i++) row[t + i * 256] = rnaf(v[i] * inv);
}

__device__ __forceinline__ float gelu_tanh(float x) {
    float x3 = x * x * x;
    return 0.5f * x * (1.0f + tanhf(0.7978845608028654f * (x + 0.044715f * x3)));
}

// ---------------------------------------------------------------------------
// tf32 mma.sync GEMM: cp.async 4-stage + ldmatrix. BM=128, BN=128, BK=16.
// 256 thr = 8 warps (2m x 4n), warp tile 64x32. 2 CTAs/SM.
// A smem [m][k] stride 20 (ldmatrix). B NT [n][k] stride 20 (ldmatrix).
// B NN [k][n] stride 136 (scalar LDS, conflict-free).
// EPI 1:*alpha | 2: rna (PV->cat) | 3: xres+gate*(acc+bias) | 4: h|gelu->cat
// ---------------------------------------------------------------------------
#define CPA16(dst, src) \
    asm volatile("cp.async.cg.shared.global [%0], [%1], 16;" :: "r"(dst), "l"(src))
#define CP_COMMIT() asm volatile("cp.async.commit_group;" ::: "memory")
#define CP_WAIT2()  asm volatile("cp.async.wait_group 2;" ::: "memory")

__device__ __forceinline__ void mma_tf32(float c[4], const uint32_t a[4],
                                         const uint32_t b[2]) {
    asm volatile(
        "mma.sync.aligned.m16n8k8.row.col.f32.tf32.tf32.f32 "
        "{%0,%1,%2,%3}, {%4,%5,%6,%7}, {%8,%9}, {%0,%1,%2,%3};"
        : "+f"(c[0]), "+f"(c[1]), "+f"(c[2]), "+f"(c[3])
        : "r"(a[0]), "r"(a[1]), "r"(a[2]), "r"(a[3]), "r"(b[0]), "r"(b[1]));
}
__device__ __forceinline__ void ldsm4(uint32_t* r, uint32_t addr) {
    asm volatile("ldmatrix.sync.aligned.m8n8.x4.shared.b16 {%0,%1,%2,%3}, [%4];"
                 : "=r"(r[0]), "=r"(r[1]), "=r"(r[2]), "=r"(r[3]) : "r"(addr));
}

template <int EPI, bool NT>
__global__ __launch_bounds__(256, 2) void gemm_cp(
    const float* __restrict__ A, const float* __restrict__ B, float* __restrict__ C,
    float* __restrict__ C2,
    int K, int lda, int ldb, int ldc,
    long long sA, long long sB, long long sC, float alpha,
    const float* __restrict__ bias, const float* __restrict__ xres,
    const float* __restrict__ gate)
{
    constexpr int BN = 128;
    constexpr int AW = 128 * 20;
    constexpr int BW = NT ? BN * 20 : 16 * (BN + 8);
    constexpr int STGW = AW + BW;
    constexpr int NJ = 4;
    extern __shared__ float sm[];

    A += (long long)blockIdx.z * sA;
    B += (long long)blockIdx.z * sB;
    C += (long long)blockIdx.z * sC;
    const int m0 = blockIdx.x * 128, n0 = blockIdx.y * BN;
    const int tid = threadIdx.x;
    const int warp = tid >> 5, lane = tid & 31;
    const int wm = (warp & 1) * 64;
    const int wn = (warp >> 1) * 32;
    const int g = lane >> 2, q = lane & 3;

    const uint32_t sbase = (uint32_t)__cvta_generic_to_shared(sm);

    // ldmatrix byte offsets (stage-relative)
    int aoff[4][2];
#pragma unroll
    for (int mi = 0; mi < 4; mi++)
#pragma unroll
        for (int ksp = 0; ksp < 2; ksp++)
            aoff[mi][ksp] = ((wm + mi * 16 + ((lane >> 3) & 1) * 8 + (lane & 7)) * 20
                             + ksp * 8 + ((lane >> 4) & 1) * 4) * 4;
    int boff[2][2];
    if (NT) {
#pragma unroll
        for (int njp = 0; njp < 2; njp++)
#pragma unroll
            for (int ksp = 0; ksp < 2; ksp++)
                boff[njp][ksp] = AW * 4 +
                    ((wn + njp * 16 + ((lane >> 4) & 1) * 8 + (lane & 7)) * 20
                     + ksp * 8 + ((lane >> 3) & 1) * 4) * 4;
    }

    float acc[4][NJ][4];
#pragma unroll
    for (int mi = 0; mi < 4; mi++)
#pragma unroll
        for (int nj = 0; nj < NJ; nj++)
#pragma unroll
            for (int e = 0; e < 4; e++) acc[mi][nj][e] = 0.f;

    const int nk = K >> 4;

    auto issue = [&](int kt, int s) {
        const uint32_t as = sbase + (uint32_t)(s * STGW * 4);
        const uint32_t bs = as + AW * 4;
        const int k0 = kt << 4;
#pragma unroll
        for (int i = 0; i < 2; i++) {
            int ch = tid + 256 * i;
            int r = ch >> 2, c = ch & 3;
            CPA16(as + (uint32_t)(r * 80 + c * 16),
                  A + (size_t)(m0 + r) * lda + k0 + c * 4);
        }
        if (NT) {   // 128 rows x 16 k = 512 chunks
#pragma unroll
            for (int i = 0; i < 2; i++) {
                int ch = tid + 256 * i;
                int r = ch >> 2, c = ch & 3;
                CPA16(bs + (uint32_t)(r * 80 + c * 16),
                      B + (size_t)(n0 + r) * ldb + k0 + c * 4);
            }
        } else {    // 16 k x 128 cols = 512 chunks
#pragma unroll
            for (int i = 0; i < 2; i++) {
                int ch = tid + 256 * i;
                int r = ch >> 5, c = ch & 31;
                CPA16(bs + (uint32_t)(r * 136 * 4 + c * 16),
                      B + (size_t)(k0 + r) * ldb + n0 + c * 4);
            }
        }
    };

    for (int s = 0; s < 3; s++) {
        if (s < nk) issue(s, s);
        CP_COMMIT();
    }

    for (int it = 0; it < nk; it++) {
        CP_WAIT2();
        __syncthreads();
        if (it + 3 < nk) issue(it + 3, (it + 3) & 3);
        CP_COMMIT();

        const uint32_t stg_u = sbase + (uint32_t)((it & 3) * STGW * 4);
        const float* bs = sm + (size_t)(it & 3) * STGW + AW;
#pragma unroll
        for (int ksp = 0; ksp < 2; ksp++) {
            const int kq = ksp * 8 + q;
            uint32_t af[4][4];
#pragma unroll
            for (int mi = 0; mi < 4; mi++) ldsm4(af[mi], stg_u + aoff[mi][ksp]);
            uint32_t bf[NJ][2];
            if (NT) {
#pragma unroll
                for (int njp = 0; njp < 2; njp++) {
                    uint32_t t4[4];
                    ldsm4(t4, stg_u + boff[njp][ksp]);
                    bf[2 * njp][0]     = t4[0];
                    bf[2 * njp][1]     = t4[1];
                    bf[2 * njp + 1][0] = t4[2];
                    bf[2 * njp + 1][1] = t4[3];
                }
            } else {
#pragma unroll
                for (int nj = 0; nj < NJ; nj++) {
                    const float* bp = bs + kq * 136 + wn + nj * 8 + g;
                    bf[nj][0] = __float_as_uint(bp[0]);
                    bf[nj][1] = __float_as_uint(bp[4 * 136]);
                }
            }
#pragma unroll
            for (int mi = 0; mi < 4; mi++)
#pragma unroll
                for (int nj = 0; nj < NJ; nj++)
                    mma_tf32(acc[mi][nj], af[mi], bf[nj]);
        }
    }

    // epilogue
#pragma unroll
    for (int mi = 0; mi < 4; mi++) {
#pragma unroll
        for (int hh = 0; hh < 2; hh++) {
            size_t row = (size_t)(m0 + wm + mi * 16 + g + hh * 8);
#pragma unroll
            for (int nj = 0; nj < NJ; nj++) {
                int col = n0 + wn + nj * 8 + 2 * q;
                float v0 = acc[mi][nj][hh * 2 + 0];
                float v1 = acc[mi][nj][hh * 2 + 1];
                if (EPI == 1) {
                    v0 *= alpha; v1 *= alpha;
                    *(float2*)(C + row * ldc + col) = make_float2(v0, v1);
                } else if (EPI == 2) {
                    *(float2*)(C + row * ldc + col) = make_float2(rnaf(v0), rnaf(v1));
                } else if (EPI == 3) {
                    v0 = xres[row * ldc + col]     + gate[col]     * (v0 + bias[col]);
                    v1 = xres[row * ldc + col + 1] + gate[col + 1] * (v1 + bias[col + 1]);
                    *(float2*)(C + row * ldc + col) = make_float2(v0, v1);
                } else if (EPI == 4) {
                    v0 += bias[col]; v1 += bias[col + 1];
                    if (col < QKV_) {
                        *(float2*)(C + row * QKV_ + col) =
                            make_float2(rnaf(v0), rnaf(v1));
                    } else {
                        *(float2*)(C2 + row * CAT_ + D_ + (col - QKV_)) =
                            make_float2(rnaf(gelu_tanh(v0)), rnaf(gelu_tanh(v1)));
                    }
                }
            }
        }
    }
}

// stage bytes x4 stages
#define SMEM_NN ((128 * 20 + 16 * 136) * 4 * 4)   // 75776
#define SMEM_NT ((128 * 20 + 128 * 20) * 4 * 4)   // 81920

// ---------------------------------------------------------------------------
// launcher
// ---------------------------------------------------------------------------
extern "C" void kernel_launch(void* const* d_in, const int* in_sizes, int n_in,
                              void* d_out, int out_size) {
    const float* x      = (const float*)d_in[0];
    const float* vec    = (const float*)d_in[1];
    const float* pe     = (const float*)d_in[2];
    const float* w_mod  = (const float*)d_in[3];
    const float* b_mod  = (const float*)d_in[4];
    const float* w1     = (const float*)d_in[5];
    const float* b1     = (const float*)d_in[6];
    const float* w2     = (const float*)d_in[7];
    const float* b2     = (const float*)d_in[8];
    const float* qscale = (const float*)d_in[9];
    const float* kscale = (const float*)d_in[10];
    float* out = (float*)d_out;

    float *sv, *m, *xmod, *h, *S, *cat, *w1r, *w2r;
    cudaGetSymbolAddress((void**)&sv,   g_sv);
    cudaGetSymbolAddress((void**)&m,    g_m);
    cudaGetSymbolAddress((void**)&xmod, g_xmod);
    cudaGetSymbolAddress((void**)&h,    g_h);
    cudaGetSymbolAddress((void**)&S,    g_S);
    cudaGetSymbolAddress((void**)&cat,  g_cat);
    cudaGetSymbolAddress((void**)&w1r,  g_w1r);
    cudaGetSymbolAddress((void**)&w2r,  g_w2r);

    cudaFuncSetAttribute(gemm_cp<4, false>,
                         cudaFuncAttributeMaxDynamicSharedMemorySize, SMEM_NN);
    cudaFuncSetAttribute(gemm_cp<1, true>,
                         cudaFuncAttributeMaxDynamicSharedMemorySize, SMEM_NT);
    cudaFuncSetAttribute(gemm_cp<2, false>,
                         cudaFuncAttributeMaxDynamicSharedMemorySize, SMEM_NN);
    cudaFuncSetAttribute(gemm_cp<3, false>,
                         cudaFuncAttributeMaxDynamicSharedMemorySize, SMEM_NN);

    // 0. pre-round weights to tf32 (overlaps nothing but is cheap & parallel)
    wround<<<592, 256>>>((const float4*)w1, (float4*)w1r, (int)((size_t)D_ * W1N_ / 4));
    wround<<<592, 256>>>((const float4*)w2, (float4*)w2r, (int)((size_t)CAT_ * D_ / 4));
    // 1. sv = silu(vec); m = b_mod
    silu_init<<<(3 * D_) / 256, 256>>>(vec, b_mod, sv, m);
    // 2. m += sv @ w_mod
    mod_gemv<<<dim3(72, 8), 128>>>(sv, w_mod, m);
    // 3. layernorm + modulate (rounded)
    ln_mod<<<L_, 256>>>(x, m, xmod);
    // 4. GEMM1: qkv -> h, gelu(mlp) -> cat[:, D:]
    gemm_cp<4, false><<<dim3(L_ / 128, W1N_ / 128), 256, SMEM_NN>>>(
        xmod, w1r, h, cat, D_, D_, W1N_, 0, 0, 0, 0, 1.0f, b1, nullptr, nullptr);
    // 5. q/k rmsnorm + rope (rounded)
    rmsrope<<<dim3(L_, H_), 64>>>(h, pe, qscale, kscale);
    // 6. S = Q @ K^T * Dh^-0.5
    gemm_cp<1, true><<<dim3(L_ / 128, L_ / 128, H_), 256, SMEM_NT>>>(
        h, h + D_, S, nullptr, DH_, QKV_, QKV_, L_,
        (long long)DH_, (long long)DH_, (long long)L_ * L_,
        0.08838834764831845f, nullptr, nullptr, nullptr);
    // 7. softmax (rounded probs)
    softmax2048<<<H_ * L_, 256>>>(S);
    // 8. PV: attn -> cat[:, 0:D]
    gemm_cp<2, false><<<dim3(L_ / 128, 1, H_), 256, SMEM_NN>>>(
        S, h + 2 * D_, cat, nullptr, L_, L_, QKV_, CAT_,
        (long long)L_ * L_, (long long)DH_, (long long)DH_,
        1.0f, nullptr, nullptr, nullptr);
    // 9. out = x + gate * (cat @ w2 + b2)
    gemm_cp<3, false><<<dim3(L_ / 128, D_ / 128), 256, SMEM_NN>>>(
        cat, w2r, out, nullptr, CAT_, CAT_, D_, D_, 0, 0, 0, 1.0f, b2, x, m + 2 * D_);
}